// round 2
// baseline (speedup 1.0000x reference)
#include <cuda_runtime.h>
#include <cstdint>

// Problem constants
#define Bb 8
#define Tt 96
#define Ss 192
#define Dd 512
#define ROWS (Bb*Tt)      // 768
#define UROWS (Bb*Ss)     // 1536

// Scratch (no dynamic allocation allowed)
__device__ float g_wq[ROWS * Dd];        // inputs @ Wq^T          [768,512]
__device__ float g_uh[UROWS * Dd];       // mems @ Wc^T + bc       [1536,512]
__device__ float g_cat[ROWS * 2 * Dd];   // [context | inputs]     [768,1024]

__device__ __forceinline__ float tanh_ap(float x) {
    float y;
    asm("tanh.approx.f32 %0, %1;" : "=f"(y) : "f"(x));
    return y;
}

#define NEG_INF (-__int_as_float(0x7f800000))

// ---------------------------------------------------------------------------
// C[M,N] = A[M,K] @ W[N,K]^T (+ bias[N])     (both operands K-contiguous, "NT")
// BM=BN=64, BK=16, 256 threads, 4x4 microtile per thread.
// M % 64 == 0, N % 64 == 0, K % 16 == 0 guaranteed by caller.
// ---------------------------------------------------------------------------
__global__ void gemm_nt(const float* __restrict__ A,
                        const float* __restrict__ W,
                        const float* __restrict__ bias,
                        float* __restrict__ C,
                        int M, int N, int K) {
    __shared__ float As[16][64];   // [k][m]
    __shared__ float Ws[16][64];   // [k][n]

    const int tid = threadIdx.x;
    const int block_m = blockIdx.y * 64;
    const int block_n = blockIdx.x * 64;
    const int tx = tid & 15;          // n-subtile
    const int ty = tid >> 4;          // m-subtile

    // loader mapping: one float4 of A and one of W per thread per k-tile
    const int lr = tid >> 2;          // 0..63 row within tile
    const int lk = (tid & 3) * 4;     // 0,4,8,12

    const float* Ap = A + (size_t)(block_m + lr) * K + lk;
    const float* Wp = W + (size_t)(block_n + lr) * K + lk;

    float acc[4][4];
#pragma unroll
    for (int i = 0; i < 4; i++)
#pragma unroll
        for (int j = 0; j < 4; j++) acc[i][j] = 0.f;

    for (int k0 = 0; k0 < K; k0 += 16) {
        float4 a4 = *reinterpret_cast<const float4*>(Ap + k0);
        float4 w4 = *reinterpret_cast<const float4*>(Wp + k0);
        As[lk + 0][lr] = a4.x; As[lk + 1][lr] = a4.y;
        As[lk + 2][lr] = a4.z; As[lk + 3][lr] = a4.w;
        Ws[lk + 0][lr] = w4.x; Ws[lk + 1][lr] = w4.y;
        Ws[lk + 2][lr] = w4.z; Ws[lk + 3][lr] = w4.w;
        __syncthreads();

#pragma unroll
        for (int k = 0; k < 16; k++) {
            float4 av = *reinterpret_cast<const float4*>(&As[k][ty * 4]);
            float4 wv = *reinterpret_cast<const float4*>(&Ws[k][tx * 4]);
            float a[4] = {av.x, av.y, av.z, av.w};
            float w[4] = {wv.x, wv.y, wv.z, wv.w};
#pragma unroll
            for (int i = 0; i < 4; i++)
#pragma unroll
                for (int j = 0; j < 4; j++) acc[i][j] = fmaf(a[i], w[j], acc[i][j]);
        }
        __syncthreads();
    }

#pragma unroll
    for (int j = 0; j < 4; j++) {
        const int n = block_n + tx * 4 + j;
        const float bv = bias ? bias[n] : 0.f;
#pragma unroll
        for (int i = 0; i < 4; i++) {
            const int m = block_m + ty * 4 + i;
            C[(size_t)m * N + n] = acc[i][j] + bv;
        }
    }
}

// ---------------------------------------------------------------------------
// Fused: tanh-score -> masked softmax -> align_vectors out -> context -> cat
// One block per (b, t) row. 256 threads = 8 warps.
//   warp w handles s = it*8 + w (24 iterations)
//   lane handles m = j*128 + lane*4 + c  (j=0..3, c=0..3)  -> full warp covers 512
// ---------------------------------------------------------------------------
__global__ void attn_fused(const float* __restrict__ inputs,
                           const float* __restrict__ mems,
                           const int* __restrict__ mem_masks,
                           const float* __restrict__ v,
                           float* __restrict__ out_align) {
    __shared__ float sm_logit[Ss];
    __shared__ float smw[Ss];
    __shared__ float red[256];

    const int row = blockIdx.x;          // b*T + t
    const int b = row / Tt;
    const int tid = threadIdx.x;
    const int warp = tid >> 5;
    const int lane = tid & 31;
    const int len = mem_masks[b];

    // Preload this row's wq and v into registers (per-lane m slice)
    const float* wqrow = g_wq + (size_t)row * Dd;
    float4 wqr[4], vr[4];
#pragma unroll
    for (int j = 0; j < 4; j++) {
        wqr[j] = *reinterpret_cast<const float4*>(wqrow + j * 128 + lane * 4);
        vr[j]  = *reinterpret_cast<const float4*>(v + j * 128 + lane * 4);
    }

    // Score: align[s] = sum_m v[m] * tanh(wq[m] + uh[s][m]); only for s < len
#pragma unroll 1
    for (int it = 0; it < Ss / 8; it++) {
        const int s = it * 8 + warp;
        if (s < len) {
            const float* uhp = g_uh + (size_t)(b * Ss + s) * Dd;
            float acc = 0.f;
#pragma unroll
            for (int j = 0; j < 4; j++) {
                float4 u = *reinterpret_cast<const float4*>(uhp + j * 128 + lane * 4);
                acc = fmaf(vr[j].x, tanh_ap(wqr[j].x + u.x), acc);
                acc = fmaf(vr[j].y, tanh_ap(wqr[j].y + u.y), acc);
                acc = fmaf(vr[j].z, tanh_ap(wqr[j].z + u.z), acc);
                acc = fmaf(vr[j].w, tanh_ap(wqr[j].w + u.w), acc);
            }
#pragma unroll
            for (int o = 16; o; o >>= 1) acc += __shfl_xor_sync(0xFFFFFFFFu, acc, o);
            if (lane == 0) sm_logit[s] = acc;
        }
    }
    __syncthreads();

    // Masked softmax over S (valid s in [0, len))
    const bool valid = (tid < Ss) && (tid < len);
    float x = valid ? sm_logit[tid] : NEG_INF;
    red[tid] = x;
    __syncthreads();
#pragma unroll
    for (int s = 128; s > 0; s >>= 1) {
        if (tid < s) red[tid] = fmaxf(red[tid], red[tid + s]);
        __syncthreads();
    }
    const float mx = red[0];
    __syncthreads();

    const float e = valid ? __expf(x - mx) : 0.f;
    red[tid] = e;
    __syncthreads();
#pragma unroll
    for (int s = 128; s > 0; s >>= 1) {
        if (tid < s) red[tid] += red[tid + s];
        __syncthreads();
    }
    const float rsum = 1.f / red[0];

    if (tid < Ss) {
        const float w = e * rsum;
        smw[tid] = w;
        out_align[(size_t)row * Ss + tid] = w;
    }
    __syncthreads();

    // Context: c[d] = sum_s w[s] * mems[b][s][d]; each thread owns a float2
    const int d0 = tid * 2;
    const float* mb = mems + (size_t)b * Ss * Dd + d0;
    float cx = 0.f, cy = 0.f;
#pragma unroll 4
    for (int s = 0; s < Ss; s += 4) {
        float4 w4 = *reinterpret_cast<const float4*>(&smw[s]);
        float2 m0 = *reinterpret_cast<const float2*>(mb + (size_t)(s + 0) * Dd);
        float2 m1 = *reinterpret_cast<const float2*>(mb + (size_t)(s + 1) * Dd);
        float2 m2 = *reinterpret_cast<const float2*>(mb + (size_t)(s + 2) * Dd);
        float2 m3 = *reinterpret_cast<const float2*>(mb + (size_t)(s + 3) * Dd);
        cx = fmaf(w4.x, m0.x, cx); cy = fmaf(w4.x, m0.y, cy);
        cx = fmaf(w4.y, m1.x, cx); cy = fmaf(w4.y, m1.y, cy);
        cx = fmaf(w4.z, m2.x, cx); cy = fmaf(w4.z, m2.y, cy);
        cx = fmaf(w4.w, m3.x, cx); cy = fmaf(w4.w, m3.y, cy);
    }

    float* catrow = g_cat + (size_t)row * (2 * Dd);
    float2 c2; c2.x = cx; c2.y = cy;
    *reinterpret_cast<float2*>(catrow + d0) = c2;
    *reinterpret_cast<float2*>(catrow + Dd + d0) =
        *reinterpret_cast<const float2*>(inputs + (size_t)row * Dd + d0);
}

// ---------------------------------------------------------------------------
extern "C" void kernel_launch(void* const* d_in, const int* in_sizes, int n_in,
                              void* d_out, int out_size) {
    const float* inputs    = (const float*)d_in[0];   // [8,96,512]
    const float* mems      = (const float*)d_in[1];   // [8,192,512]
    const int*   mem_masks = (const int*)d_in[2];     // [8]
    const float* Wq        = (const float*)d_in[3];   // [512,512]
    const float* Wc        = (const float*)d_in[4];   // [512,512]
    const float* bc        = (const float*)d_in[5];   // [512]
    const float* v         = (const float*)d_in[6];   // [512]
    const float* Wout      = (const float*)d_in[7];   // [512,1024]
    const float* bout      = (const float*)d_in[8];   // [512]

    float* out_attn  = (float*)d_out;                  // [768,512]
    float* out_align = (float*)d_out + ROWS * Dd;      // [768,192]

    float *wq_p, *uh_p, *cat_p;
    cudaGetSymbolAddress((void**)&wq_p,  g_wq);
    cudaGetSymbolAddress((void**)&uh_p,  g_uh);
    cudaGetSymbolAddress((void**)&cat_p, g_cat);

    // wq = inputs @ Wq^T          [768,512] x [512,512]
    gemm_nt<<<dim3(Dd / 64, ROWS / 64), 256>>>(inputs, Wq, nullptr, wq_p,
                                               ROWS, Dd, Dd);
    // uh = mems @ Wc^T + bc       [1536,512] x [512,512]
    gemm_nt<<<dim3(Dd / 64, UROWS / 64), 256>>>(mems, Wc, bc, uh_p,
                                                UROWS, Dd, Dd);
    // fused score/softmax/context/concat
    attn_fused<<<ROWS, 256>>>(inputs, mems, mem_masks, v, out_align);

    // attn_h = cat @ Wout^T + bout   [768,1024] x [512,1024]
    gemm_nt<<<dim3(Dd / 64, ROWS / 64), 256>>>(cat_p, Wout, bout, out_attn,
                                               ROWS, Dd, 2 * Dd);
}

// round 5
// speedup vs baseline: 1.3530x; 1.3530x over previous
#include <cuda_runtime.h>
#include <cstdint>

#define Bb 8
#define Tt 96
#define Ss 192
#define Dd 512
#define ROWS (Bb*Tt)      // 768
#define UROWS (Bb*Ss)     // 1536

// Scratch
__device__ float g_wq[ROWS * Dd];        // inputs @ Wq^T                 [768,512]
__device__ float g_uh[UROWS * Dd];       // mems @ Wc^T + bc              [1536,512]
__device__ float g_part[ROWS * Dd];      // inputs @ Wout[:,512:]^T + bout[768,512]
__device__ float g_c[ROWS * Dd];         // context                       [768,512]

#define NEG_INF (-__int_as_float(0x7f800000))

__device__ __forceinline__ float tanh_ap(float x) {
    float y;
    asm("tanh.approx.f32 %0, %1;" : "=f"(y) : "f"(x));
    return y;
}
__device__ __forceinline__ unsigned long long ffma2(unsigned long long a,
                                                    unsigned long long b,
                                                    unsigned long long c) {
    unsigned long long d;
    asm("fma.rn.f32x2 %0, %1, %2, %3;" : "=l"(d) : "l"(a), "l"(b), "l"(c));
    return d;
}
__device__ __forceinline__ unsigned long long dup2(float x) {
    unsigned long long d;
    asm("mov.b64 %0, {%1, %1};" : "=l"(d) : "f"(x));
    return d;
}
__device__ __forceinline__ float2 unpk(unsigned long long p) {
    float lo, hi;
    asm("mov.b64 {%0, %1}, %2;" : "=f"(lo), "=f"(hi) : "l"(p));
    return make_float2(lo, hi);
}

// ---------------------------------------------------------------------------
// f32x2-packed GEMM body.  C[BMxBN tile] = A[M,512] @ W'[512-slice]^T
// N = 512 fixed, K = 512 fixed, BN = 64, BK = 16, 256 threads.
// BM = 128: microtile 8m x 4n (4 m-pairs). BM = 64: 4m x 4n (2 m-pairs).
// smem k-major with pad 4 -> rows stay 16B aligned, store conflicts <= 2-way.
// ---------------------------------------------------------------------------
template <int BM>
__device__ __forceinline__ void gemm_body(
    float (*As)[BM + 4], float (*Ws)[68],
    const float* __restrict__ A, int lda,
    const float* __restrict__ W, int ldw,
    const float* __restrict__ bias,
    const float* __restrict__ part,
    float* __restrict__ C,
    int bm, int bn)
{
    constexpr int MT = BM / 16;    // 8 or 4
    constexpr int P  = MT / 2;     // 4 or 2

    const int tid = threadIdx.x;
    const int tx = tid & 15;
    const int ty = tid >> 4;
    const int lr = tid >> 2;         // 0..63
    const int lk = (tid & 3) * 4;    // 0,4,8,12

    const float* Ap0 = A + (size_t)(bm + lr) * lda + lk;
    const float* Ap1 = A + (size_t)(bm + lr + 64) * lda + lk;   // BM==128 only
    const float* Wp  = W + (size_t)(bn + lr) * ldw + lk;

    unsigned long long acc[P][4];
#pragma unroll
    for (int p = 0; p < P; p++)
#pragma unroll
        for (int j = 0; j < 4; j++) acc[p][j] = 0ull;

#pragma unroll 1
    for (int k0 = 0; k0 < Dd; k0 += 16) {
        float4 a0 = *reinterpret_cast<const float4*>(Ap0 + k0);
        As[lk + 0][lr] = a0.x; As[lk + 1][lr] = a0.y;
        As[lk + 2][lr] = a0.z; As[lk + 3][lr] = a0.w;
        if (BM == 128) {
            float4 a1 = *reinterpret_cast<const float4*>(Ap1 + k0);
            As[lk + 0][lr + 64] = a1.x; As[lk + 1][lr + 64] = a1.y;
            As[lk + 2][lr + 64] = a1.z; As[lk + 3][lr + 64] = a1.w;
        }
        float4 wv = *reinterpret_cast<const float4*>(Wp + k0);
        Ws[lk + 0][lr] = wv.x; Ws[lk + 1][lr] = wv.y;
        Ws[lk + 2][lr] = wv.z; Ws[lk + 3][lr] = wv.w;
        __syncthreads();

#pragma unroll
        for (int k = 0; k < 16; k++) {
            // A pairs: direct f32x2 loads from smem (m-contiguous)
            unsigned long long ap[P];
            const float* ar = &As[k][ty * MT];
#pragma unroll
            for (int p = 0; p < P; p++)
                ap[p] = *reinterpret_cast<const unsigned long long*>(ar + 2 * p);
            float4 w4 = *reinterpret_cast<const float4*>(&Ws[k][tx * 4]);
            unsigned long long wd[4] = {dup2(w4.x), dup2(w4.y), dup2(w4.z), dup2(w4.w)};
#pragma unroll
            for (int p = 0; p < P; p++)
#pragma unroll
                for (int j = 0; j < 4; j++)
                    acc[p][j] = ffma2(ap[p], wd[j], acc[p][j]);
        }
        __syncthreads();
    }

#pragma unroll
    for (int j = 0; j < 4; j++) {
        const int n = bn + tx * 4 + j;
        const float bv = bias ? bias[n] : 0.f;
#pragma unroll
        for (int p = 0; p < P; p++) {
            const int m = bm + ty * MT + 2 * p;
            float2 val = unpk(acc[p][j]);
            float v0 = val.x + bv, v1 = val.y + bv;
            if (part) {
                v0 += part[(size_t)m * Dd + n];
                v1 += part[(size_t)(m + 1) * Dd + n];
            }
            C[(size_t)m * Dd + n] = v0;
            C[(size_t)(m + 1) * Dd + n] = v1;
        }
    }
}

// ---------------------------------------------------------------------------
// Fused launch 1: three independent GEMMs in one grid (192 blocks).
//   [0,48):    g_wq   = inputs @ Wq^T                       (6x8 tiles of 128x64)
//   [48,144):  g_uh   = mems @ Wc^T + bc                    (12x8)
//   [144,192): g_part = inputs @ Wout[:,512:]^T + bout      (6x8)
// ---------------------------------------------------------------------------
__global__ __launch_bounds__(256) void mega_gemm1(
    const float* __restrict__ inputs, const float* __restrict__ mems,
    const float* __restrict__ Wq, const float* __restrict__ Wc,
    const float* __restrict__ bc, const float* __restrict__ Wout,
    const float* __restrict__ bout)
{
    __shared__ float As[16][132];
    __shared__ float Ws[16][68];
    const int bx = blockIdx.x;
    if (bx < 48) {
        gemm_body<128>(As, Ws, inputs, Dd, Wq, Dd, nullptr, nullptr, g_wq,
                       (bx >> 3) * 128, (bx & 7) * 64);
    } else if (bx < 144) {
        const int t = bx - 48;
        gemm_body<128>(As, Ws, mems, Dd, Wc, Dd, bc, nullptr, g_uh,
                       (t >> 3) * 128, (t & 7) * 64);
    } else {
        const int t = bx - 144;
        gemm_body<128>(As, Ws, inputs, Dd, Wout + Dd, 2 * Dd, bout, nullptr, g_part,
                       (t >> 3) * 128, (t & 7) * 64);
    }
}

// Launch 3: attn_h = c @ Wout[:, :512]^T + g_part   (96 blocks, 64x64 tiles)
__global__ __launch_bounds__(256) void gemm2(const float* __restrict__ Wout,
                                             float* __restrict__ out_attn)
{
    __shared__ float As[16][68];
    __shared__ float Ws[16][68];
    gemm_body<64>(As, Ws, g_c, Dd, Wout, 2 * Dd, nullptr, g_part, out_attn,
                  (blockIdx.x >> 3) * 64, (blockIdx.x & 7) * 64);
}

// ---------------------------------------------------------------------------
// Fused: tanh-score -> masked softmax -> align out -> context -> g_c
// One block per (b,t). 256 threads = 8 warps.
// ---------------------------------------------------------------------------
__global__ __launch_bounds__(256) void attn_fused(
    const float* __restrict__ mems, const int* __restrict__ mem_masks,
    const float* __restrict__ v, float* __restrict__ out_align)
{
    __shared__ float sm_logit[Ss];
    __shared__ float smw[Ss];
    __shared__ float red[256];

    const int row = blockIdx.x;
    const int b = row / Tt;
    const int tid = threadIdx.x;
    const int warp = tid >> 5;
    const int lane = tid & 31;
    const int len = mem_masks[b];

    const float* wqrow = g_wq + (size_t)row * Dd;
    float4 wqr[4], vr[4];
#pragma unroll
    for (int j = 0; j < 4; j++) {
        wqr[j] = *reinterpret_cast<const float4*>(wqrow + j * 128 + lane * 4);
        vr[j]  = *reinterpret_cast<const float4*>(v + j * 128 + lane * 4);
    }

#pragma unroll 1
    for (int it = 0; it < Ss / 8; it++) {
        const int s = it * 8 + warp;
        if (s < len) {
            const float* uhp = g_uh + (size_t)(b * Ss + s) * Dd;
            float acc = 0.f;
#pragma unroll
            for (int j = 0; j < 4; j++) {
                float4 u = *reinterpret_cast<const float4*>(uhp + j * 128 + lane * 4);
                acc = fmaf(vr[j].x, tanh_ap(wqr[j].x + u.x), acc);
                acc = fmaf(vr[j].y, tanh_ap(wqr[j].y + u.y), acc);
                acc = fmaf(vr[j].z, tanh_ap(wqr[j].z + u.z), acc);
                acc = fmaf(vr[j].w, tanh_ap(wqr[j].w + u.w), acc);
            }
#pragma unroll
            for (int o = 16; o; o >>= 1) acc += __shfl_xor_sync(0xFFFFFFFFu, acc, o);
            if (lane == 0) sm_logit[s] = acc;
        }
    }
    __syncthreads();

    const bool valid = (tid < Ss) && (tid < len);
    float x = valid ? sm_logit[tid] : NEG_INF;
    red[tid] = x;
    __syncthreads();
#pragma unroll
    for (int s = 128; s > 0; s >>= 1) {
        if (tid < s) red[tid] = fmaxf(red[tid], red[tid + s]);
        __syncthreads();
    }
    const float mx = red[0];
    __syncthreads();

    const float e = valid ? __expf(x - mx) : 0.f;
    red[tid] = e;
    __syncthreads();
#pragma unroll
    for (int s = 128; s > 0; s >>= 1) {
        if (tid < s) red[tid] += red[tid + s];
        __syncthreads();
    }
    const float rsum = 1.f / red[0];

    if (tid < Ss) {
        const float w = e * rsum;
        smw[tid] = w;
        out_align[(size_t)row * Ss + tid] = w;
    }
    __syncthreads();

    // context: each thread owns float2 of d
    const int d0 = tid * 2;
    const float* mb = mems + (size_t)b * Ss * Dd + d0;
    float cx = 0.f, cy = 0.f;
#pragma unroll 4
    for (int s = 0; s < Ss; s += 4) {
        float4 w4 = *reinterpret_cast<const float4*>(&smw[s]);
        float2 m0 = *reinterpret_cast<const float2*>(mb + (size_t)(s + 0) * Dd);
        float2 m1 = *reinterpret_cast<const float2*>(mb + (size_t)(s + 1) * Dd);
        float2 m2 = *reinterpret_cast<const float2*>(mb + (size_t)(s + 2) * Dd);
        float2 m3 = *reinterpret_cast<const float2*>(mb + (size_t)(s + 3) * Dd);
        cx = fmaf(w4.x, m0.x, cx); cy = fmaf(w4.x, m0.y, cy);
        cx = fmaf(w4.y, m1.x, cx); cy = fmaf(w4.y, m1.y, cy);
        cx = fmaf(w4.z, m2.x, cx); cy = fmaf(w4.z, m2.y, cy);
        cx = fmaf(w4.w, m3.x, cx); cy = fmaf(w4.w, m3.y, cy);
    }
    float2 c2; c2.x = cx; c2.y = cy;
    *reinterpret_cast<float2*>(g_c + (size_t)row * Dd + d0) = c2;
}

// ---------------------------------------------------------------------------
extern "C" void kernel_launch(void* const* d_in, const int* in_sizes, int n_in,
                              void* d_out, int out_size) {
    const float* inputs    = (const float*)d_in[0];
    const float* mems      = (const float*)d_in[1];
    const int*   mem_masks = (const int*)d_in[2];
    const float* Wq        = (const float*)d_in[3];
    const float* Wc        = (const float*)d_in[4];
    const float* bc        = (const float*)d_in[5];
    const float* v         = (const float*)d_in[6];
    const float* Wout      = (const float*)d_in[7];
    const float* bout      = (const float*)d_in[8];

    float* out_attn  = (float*)d_out;               // [768,512]
    float* out_align = (float*)d_out + ROWS * Dd;   // [768,192]

    mega_gemm1<<<192, 256>>>(inputs, mems, Wq, Wc, bc, Wout, bout);
    attn_fused<<<ROWS, 256>>>(mems, mem_masks, v, out_align);
    gemm2<<<96, 256>>>(Wout, out_attn);
}